// round 15
// baseline (speedup 1.0000x reference)
#include <cuda_runtime.h>

// MakeCutouts: 32 cutouts of x[8,3,512,512] fp32, adaptive-avg-pool (torch
// bins) to 224x224. Output [256, 3, 224, 224] fp32.
//
// v11 structure (1 barrier, direct __shared__ refs, float4 phase 1 with
// register-carried <=1-row bin overlap, uniform sz<=448 MAXTAP pruning,
// 32-bit indexing) with conflict-free phase 2: aligned float2 window gather.
//   small (nx<=3): taps fit window [q, q+3], two LDS.64 per row.
//   big   (nx<=4): taps fit window [q, q+5], three LDS.64 per row
//                  (position 4 needed when off odd and nx=4).
// Selection flags row-invariant. CSTRIDE=520 (mult of 4 -> 16B-aligned rows);
// row tails [span, span+4) zeroed so window loads never read garbage.

#define OUTS   224
#define BATCH  8
#define CHAN   3
#define HW     512
#define CUTN   32
#define NPLANE (BATCH * CHAN)   // 24
#define YG     8                // output rows per block
#define NYG    (OUTS / YG)      // 28
#define BPH    4                // bins per half
#define CSTRIDE 520

__device__ __forceinline__ float inv_small(int n) {
    return n == 1 ? 1.0f : (n == 2 ? 0.5f : (n == 3 ? (1.0f / 3.0f) : 0.25f));
}

__device__ __forceinline__ void f4add(float4& a, const float4 b) {
    a.x += b.x; a.y += b.y; a.z += b.z; a.w += b.w;
}

__global__ __launch_bounds__(256)
void makecutouts_v14(const float* __restrict__ x,
                     const int* __restrict__ sizes,
                     const int* __restrict__ offy,
                     const int* __restrict__ offx,
                     float* __restrict__ out)
{
    __shared__ __align__(16) float buf[YG][CSTRIDE];   // 16,640 B
    __shared__ float invy_sh[YG];

    const int tid = threadIdx.x;
    int bid = blockIdx.x;
    const int yg    = bid % NYG;  bid /= NYG;
    const int plane = bid % NPLANE;
    const int cut   = bid / NPLANE;

    const int sz = __ldg(sizes + cut);
    const int oy = __ldg(offy + cut);
    const int ox = __ldg(offx + cut);

    const int ox_al = ox & ~3;
    const int shift = ox - ox_al;        // 0..3
    const int span  = shift + sz;        // <= 515
    const int y0 = yg * YG;

    if (tid < YG) {
        const int yy = y0 + tid;
        const int ny = ((yy + 1) * sz + (OUTS - 1)) / OUTS - (yy * sz) / OUTS;
        invy_sh[tid] = inv_small(ny);
        // zero row tail so unconditional window loads are safe
        #pragma unroll
        for (int k = 0; k < 4; k++) buf[tid][span + k] = 0.0f;
    }

    const float* pbase = x + (plane * (HW * HW) + oy * HW + ox_al);

    const int lane = tid & 127;
    const int half = tid >> 7;
    const int rem  = span - lane * 4;
    const int col4 = lane * 4;
    const int yb   = y0 + half * BPH;

    const bool small = (sz <= 448);      // uniform per block

    // ================= Phase 1 =================
    if (small) {
        if (rem >= 4) {
            float4 last; int pe = -1000;
            #pragma unroll
            for (int j = 0; j < BPH; j++) {
                const int y  = yb + j;
                const int sy = (y * sz) / OUTS;
                const int ey = ((y + 1) * sz + (OUTS - 1)) / OUTS;
                const int ny = ey - sy;           // 1..3
                const float* rp = pbase + (sy * HW + col4);

                float4 acc, l;
                if (sy == pe - 1) { acc = last; l = last; }
                else              { l = __ldg((const float4*)rp); acc = l; }
                if (ny > 1) { l = __ldg((const float4*)(rp + HW));     f4add(acc, l); }
                if (ny > 2) { l = __ldg((const float4*)(rp + 2 * HW)); f4add(acc, l); }
                *(float4*)&buf[half * BPH + j][col4] = acc;
                last = l; pe = ey;
            }
        } else if (rem > 0) {
            #pragma unroll
            for (int j = 0; j < BPH; j++) {
                const int y  = yb + j;
                const int sy = (y * sz) / OUTS;
                const int ny = ((y + 1) * sz + (OUTS - 1)) / OUTS - sy;
                const float* rp = pbase + (sy * HW + col4);
                #pragma unroll
                for (int k = 0; k < 3; k++) {
                    if (k < rem) {
                        float s = __ldg(rp + k);
                        if (ny > 1) s += __ldg(rp + k + HW);
                        if (ny > 2) s += __ldg(rp + k + 2 * HW);
                        buf[half * BPH + j][col4 + k] = s;
                    }
                }
            }
        }
    } else {
        if (rem >= 4) {
            float4 last; int pe = -1000;
            #pragma unroll
            for (int j = 0; j < BPH; j++) {
                const int y  = yb + j;
                const int sy = (y * sz) / OUTS;
                const int ey = ((y + 1) * sz + (OUTS - 1)) / OUTS;
                const int ny = ey - sy;           // 1..4
                const float* rp = pbase + (sy * HW + col4);

                float4 acc, l;
                if (sy == pe - 1) { acc = last; l = last; }
                else              { l = __ldg((const float4*)rp); acc = l; }
                if (ny > 1) { l = __ldg((const float4*)(rp + HW));     f4add(acc, l); }
                if (ny > 2) { l = __ldg((const float4*)(rp + 2 * HW)); f4add(acc, l); }
                if (ny > 3) { l = __ldg((const float4*)(rp + 3 * HW)); f4add(acc, l); }
                *(float4*)&buf[half * BPH + j][col4] = acc;
                last = l; pe = ey;
            }
        } else if (rem > 0) {
            #pragma unroll
            for (int j = 0; j < BPH; j++) {
                const int y  = yb + j;
                const int sy = (y * sz) / OUTS;
                const int ny = ((y + 1) * sz + (OUTS - 1)) / OUTS - sy;
                const float* rp = pbase + (sy * HW + col4);
                #pragma unroll
                for (int k = 0; k < 3; k++) {
                    if (k < rem) {
                        float s = __ldg(rp + k);
                        if (ny > 1) s += __ldg(rp + k + HW);
                        if (ny > 2) s += __ldg(rp + k + 2 * HW);
                        if (ny > 3) s += __ldg(rp + k + 3 * HW);
                        buf[half * BPH + j][col4 + k] = s;
                    }
                }
            }
        }
        if (span > 512 && tid == 126) {   // cols 512..514 (rare)
            #pragma unroll 1
            for (int j = 0; j < YG; j++) {
                const int y  = y0 + j;
                const int sy = (y * sz) / OUTS;
                const int ny = ((y + 1) * sz + (OUTS - 1)) / OUTS - sy;
                #pragma unroll
                for (int c = 512; c < 515; c++) {
                    if (c < span) {
                        const float* q = pbase + (sy * HW + c);
                        float s = __ldg(q);
                        if (ny > 1) s += __ldg(q + HW);
                        if (ny > 2) s += __ldg(q + 2 * HW);
                        if (ny > 3) s += __ldg(q + 3 * HW);
                        buf[j][c] = s;
                    }
                }
            }
        }
    }

    __syncthreads();

    // ===== Phase 2: conflict-free float2 window gather, two rows at a time =====
    if (tid < OUTS) {
        const int sx = (tid * sz) / OUTS;
        const int ex = ((tid + 1) * sz + (OUTS - 1)) / OUTS;
        const int nx = ex - sx;              // 1..4 (<=3 when small)
        const float invx = inv_small(nx);
        const int off = shift + sx;

        // taps occupy window positions st .. st+nx-1, q even
        const int st = off & 1;
        const int q  = off - st;
        const bool f1 = (st == 0) && (nx >= 2);   // position 1
        const bool f2 = nx >= 3 - st;             // position 2
        const bool f3 = nx >= 4 - st;             // position 3
        const bool f4 = (st == 1) && (nx >= 4);   // position 4 (big only)

        int oidx = ((cut * NPLANE + plane) * OUTS + y0) * OUTS + tid;

        if (small) {
            #pragma unroll
            for (int i = 0; i < YG; i += 2) {
                const float2 A0 = *(const float2*)&buf[i][q];
                const float2 B0 = *(const float2*)&buf[i][q + 2];
                const float2 A1 = *(const float2*)&buf[i + 1][q];
                const float2 B1 = *(const float2*)&buf[i + 1][q + 2];

                float s0 = st ? A0.y : A0.x;
                float s1 = st ? A1.y : A1.x;
                if (f1) { s0 += A0.y; s1 += A1.y; }
                if (f2) { s0 += B0.x; s1 += B1.x; }
                if (f3) { s0 += B0.y; s1 += B1.y; }

                out[oidx]        = s0 * (invx * invy_sh[i]);
                out[oidx + OUTS] = s1 * (invx * invy_sh[i + 1]);
                oidx += 2 * OUTS;
            }
        } else {
            #pragma unroll
            for (int i = 0; i < YG; i += 2) {
                const float2 A0 = *(const float2*)&buf[i][q];
                const float2 B0 = *(const float2*)&buf[i][q + 2];
                const float2 C0 = *(const float2*)&buf[i][q + 4];
                const float2 A1 = *(const float2*)&buf[i + 1][q];
                const float2 B1 = *(const float2*)&buf[i + 1][q + 2];
                const float2 C1 = *(const float2*)&buf[i + 1][q + 4];

                float s0 = st ? A0.y : A0.x;
                float s1 = st ? A1.y : A1.x;
                if (f1) { s0 += A0.y; s1 += A1.y; }
                if (f2) { s0 += B0.x; s1 += B1.x; }
                if (f3) { s0 += B0.y; s1 += B1.y; }
                if (f4) { s0 += C0.x; s1 += C1.x; }

                out[oidx]        = s0 * (invx * invy_sh[i]);
                out[oidx + OUTS] = s1 * (invx * invy_sh[i + 1]);
                oidx += 2 * OUTS;
            }
        }
    }
}

extern "C" void kernel_launch(void* const* d_in, const int* in_sizes, int n_in,
                              void* d_out, int out_size)
{
    const float* x     = (const float*)d_in[0];
    const int*   sizes = (const int*)d_in[1];
    const int*   oy    = (const int*)d_in[2];
    const int*   ox    = (const int*)d_in[3];
    float* out = (float*)d_out;

    const int blocks = CUTN * NPLANE * NYG;   // 21504
    makecutouts_v14<<<blocks, 256>>>(x, sizes, oy, ox, out);
}

// round 16
// speedup vs baseline: 1.0253x; 1.0253x over previous
#include <cuda_runtime.h>

// MakeCutouts: 32 cutouts of x[8,3,512,512] fp32, adaptive-avg-pool (torch
// bins) to 224x224. Output [256, 3, 224, 224] fp32.
//
// v14 structure (1 barrier, direct __shared__ refs, float4 phase 1 with
// register-carried <=1-row bin overlap, uniform sz<=448 MAXTAP pruning,
// 32-bit indexing, conflict-free float2-window phase 2) plus:
//  - per-bin (sy,ny) computed ONCE per thread (bin lane&3) and distributed
//    via width-4 __shfl_sync — replaces 4 block-uniform magic-div chains
//    per thread with 1 chain + 3 shuffles, no extra barrier.
//  - tail zeroing removed (phase-2 flags never include positions >= span;
//    window loads of uninitialized smem are dead values, in-bounds).

#define OUTS   224
#define BATCH  8
#define CHAN   3
#define HW     512
#define CUTN   32
#define NPLANE (BATCH * CHAN)   // 24
#define YG     8                // output rows per block
#define NYG    (OUTS / YG)      // 28
#define BPH    4                // bins per half
#define CSTRIDE 520             // mult of 4 -> 16B-aligned rows; >= 515+5

__device__ __forceinline__ float inv_small(int n) {
    return n == 1 ? 1.0f : (n == 2 ? 0.5f : (n == 3 ? (1.0f / 3.0f) : 0.25f));
}

__device__ __forceinline__ void f4add(float4& a, const float4 b) {
    a.x += b.x; a.y += b.y; a.z += b.z; a.w += b.w;
}

__global__ __launch_bounds__(256)
void makecutouts_v15(const float* __restrict__ x,
                     const int* __restrict__ sizes,
                     const int* __restrict__ offy,
                     const int* __restrict__ offx,
                     float* __restrict__ out)
{
    __shared__ __align__(16) float buf[YG][CSTRIDE];   // 16,640 B
    __shared__ float invy_sh[YG];

    const int tid = threadIdx.x;
    int bid = blockIdx.x;
    const int yg    = bid % NYG;  bid /= NYG;
    const int plane = bid % NPLANE;
    const int cut   = bid / NPLANE;

    const int sz = __ldg(sizes + cut);
    const int oy = __ldg(offy + cut);
    const int ox = __ldg(offx + cut);

    const int ox_al = ox & ~3;
    const int shift = ox - ox_al;        // 0..3
    const int span  = shift + sz;        // <= 515
    const int y0 = yg * YG;

    if (tid < YG) {
        const int yy = y0 + tid;
        const int ny = ((yy + 1) * sz + (OUTS - 1)) / OUTS - (yy * sz) / OUTS;
        invy_sh[tid] = inv_small(ny);
    }

    const float* pbase = x + (plane * (HW * HW) + oy * HW + ox_al);

    const int lane = tid & 127;
    const int half = tid >> 7;
    const int rem  = span - lane * 4;
    const int col4 = lane * 4;
    const int yb   = y0 + half * BPH;

    // ---- bin metadata: 1 div-chain per thread, width-4 shuffle broadcast ----
    // (before any divergent branch: full-warp participation)
    int mself;
    {
        const int jj = tid & 3;
        const int y  = yb + jj;
        const int sy = (y * sz) / OUTS;
        const int ny = ((y + 1) * sz + (OUTS - 1)) / OUTS - sy;   // 1..4
        mself = sy | (ny << 16);
    }
    int ms[BPH];
    ms[0] = __shfl_sync(0xffffffffu, mself, 0, 4);
    ms[1] = __shfl_sync(0xffffffffu, mself, 1, 4);
    ms[2] = __shfl_sync(0xffffffffu, mself, 2, 4);
    ms[3] = __shfl_sync(0xffffffffu, mself, 3, 4);

    const bool small = (sz <= 448);      // uniform per block

    // ================= Phase 1 =================
    if (small) {
        if (rem >= 4) {
            float4 last; int pe = -1000;
            #pragma unroll
            for (int j = 0; j < BPH; j++) {
                const int sy = ms[j] & 0xFFFF;
                const int ny = ms[j] >> 16;           // 1..3
                const float* rp = pbase + (sy * HW + col4);

                float4 acc, l;
                if (sy == pe - 1) { acc = last; l = last; }
                else              { l = __ldg((const float4*)rp); acc = l; }
                if (ny > 1) { l = __ldg((const float4*)(rp + HW));     f4add(acc, l); }
                if (ny > 2) { l = __ldg((const float4*)(rp + 2 * HW)); f4add(acc, l); }
                *(float4*)&buf[half * BPH + j][col4] = acc;
                last = l; pe = sy + ny;
            }
        } else if (rem > 0) {
            #pragma unroll
            for (int j = 0; j < BPH; j++) {
                const int sy = ms[j] & 0xFFFF;
                const int ny = ms[j] >> 16;
                const float* rp = pbase + (sy * HW + col4);
                #pragma unroll
                for (int k = 0; k < 3; k++) {
                    if (k < rem) {
                        float s = __ldg(rp + k);
                        if (ny > 1) s += __ldg(rp + k + HW);
                        if (ny > 2) s += __ldg(rp + k + 2 * HW);
                        buf[half * BPH + j][col4 + k] = s;
                    }
                }
            }
        }
    } else {
        if (rem >= 4) {
            float4 last; int pe = -1000;
            #pragma unroll
            for (int j = 0; j < BPH; j++) {
                const int sy = ms[j] & 0xFFFF;
                const int ny = ms[j] >> 16;           // 1..4
                const float* rp = pbase + (sy * HW + col4);

                float4 acc, l;
                if (sy == pe - 1) { acc = last; l = last; }
                else              { l = __ldg((const float4*)rp); acc = l; }
                if (ny > 1) { l = __ldg((const float4*)(rp + HW));     f4add(acc, l); }
                if (ny > 2) { l = __ldg((const float4*)(rp + 2 * HW)); f4add(acc, l); }
                if (ny > 3) { l = __ldg((const float4*)(rp + 3 * HW)); f4add(acc, l); }
                *(float4*)&buf[half * BPH + j][col4] = acc;
                last = l; pe = sy + ny;
            }
        } else if (rem > 0) {
            #pragma unroll
            for (int j = 0; j < BPH; j++) {
                const int sy = ms[j] & 0xFFFF;
                const int ny = ms[j] >> 16;
                const float* rp = pbase + (sy * HW + col4);
                #pragma unroll
                for (int k = 0; k < 3; k++) {
                    if (k < rem) {
                        float s = __ldg(rp + k);
                        if (ny > 1) s += __ldg(rp + k + HW);
                        if (ny > 2) s += __ldg(rp + k + 2 * HW);
                        if (ny > 3) s += __ldg(rp + k + 3 * HW);
                        buf[half * BPH + j][col4 + k] = s;
                    }
                }
            }
        }
        if (span > 512 && tid == 126) {   // cols 512..514 (rare)
            #pragma unroll 1
            for (int j = 0; j < YG; j++) {
                const int y  = y0 + j;
                const int sy = (y * sz) / OUTS;
                const int ny = ((y + 1) * sz + (OUTS - 1)) / OUTS - sy;
                #pragma unroll
                for (int c = 512; c < 515; c++) {
                    if (c < span) {
                        const float* q = pbase + (sy * HW + c);
                        float s = __ldg(q);
                        if (ny > 1) s += __ldg(q + HW);
                        if (ny > 2) s += __ldg(q + 2 * HW);
                        if (ny > 3) s += __ldg(q + 3 * HW);
                        buf[j][c] = s;
                    }
                }
            }
        }
    }

    __syncthreads();

    // ===== Phase 2: conflict-free float2 window gather, two rows at a time =====
    if (tid < OUTS) {
        const int sx = (tid * sz) / OUTS;
        const int ex = ((tid + 1) * sz + (OUTS - 1)) / OUTS;
        const int nx = ex - sx;              // 1..4 (<=3 when small)
        const float invx = inv_small(nx);
        const int off = shift + sx;

        // taps occupy window positions st .. st+nx-1, q even
        const int st = off & 1;
        const int q  = off - st;
        const bool f1 = (st == 0) && (nx >= 2);   // position 1
        const bool f2 = nx >= 3 - st;             // position 2
        const bool f3 = nx >= 4 - st;             // position 3
        const bool f4 = (st == 1) && (nx >= 4);   // position 4 (big only)

        int oidx = ((cut * NPLANE + plane) * OUTS + y0) * OUTS + tid;

        if (small) {
            #pragma unroll
            for (int i = 0; i < YG; i += 2) {
                const float2 A0 = *(const float2*)&buf[i][q];
                const float2 B0 = *(const float2*)&buf[i][q + 2];
                const float2 A1 = *(const float2*)&buf[i + 1][q];
                const float2 B1 = *(const float2*)&buf[i + 1][q + 2];

                float s0 = st ? A0.y : A0.x;
                float s1 = st ? A1.y : A1.x;
                if (f1) { s0 += A0.y; s1 += A1.y; }
                if (f2) { s0 += B0.x; s1 += B1.x; }
                if (f3) { s0 += B0.y; s1 += B1.y; }

                out[oidx]        = s0 * (invx * invy_sh[i]);
                out[oidx + OUTS] = s1 * (invx * invy_sh[i + 1]);
                oidx += 2 * OUTS;
            }
        } else {
            #pragma unroll
            for (int i = 0; i < YG; i += 2) {
                const float2 A0 = *(const float2*)&buf[i][q];
                const float2 B0 = *(const float2*)&buf[i][q + 2];
                const float2 C0 = *(const float2*)&buf[i][q + 4];
                const float2 A1 = *(const float2*)&buf[i + 1][q];
                const float2 B1 = *(const float2*)&buf[i + 1][q + 2];
                const float2 C1 = *(const float2*)&buf[i + 1][q + 4];

                float s0 = st ? A0.y : A0.x;
                float s1 = st ? A1.y : A1.x;
                if (f1) { s0 += A0.y; s1 += A1.y; }
                if (f2) { s0 += B0.x; s1 += B1.x; }
                if (f3) { s0 += B0.y; s1 += B1.y; }
                if (f4) { s0 += C0.x; s1 += C1.x; }

                out[oidx]        = s0 * (invx * invy_sh[i]);
                out[oidx + OUTS] = s1 * (invx * invy_sh[i + 1]);
                oidx += 2 * OUTS;
            }
        }
    }
}

extern "C" void kernel_launch(void* const* d_in, const int* in_sizes, int n_in,
                              void* d_out, int out_size)
{
    const float* x     = (const float*)d_in[0];
    const int*   sizes = (const int*)d_in[1];
    const int*   oy    = (const int*)d_in[2];
    const int*   ox    = (const int*)d_in[3];
    float* out = (float*)d_out;

    const int blocks = CUTN * NPLANE * NYG;   // 21504
    makecutouts_v15<<<blocks, 256>>>(x, sizes, oy, ox, out);
}